// round 7
// baseline (speedup 1.0000x reference)
#include <cuda_runtime.h>
#include <math.h>

#define SEQ 2048
#define DMODEL 1024
#define QH 16
#define KVH 4
#define DH 64
#define TOPK 64

// ---------------- scratch (__device__ globals; no allocations) ----------------
__device__ double g_Qd[SEQ * QH * DH];   // 16 MB  roped q, fp64 (true values)
__device__ double g_Kd[SEQ * KVH * DH];  // 4 MB   roped k, fp64
__device__ float g_V[SEQ * KVH * DH];    // 2 MB
__device__ float g_AO[SEQ * QH * DH];    // 8 MB
__device__ float g_cos[SEQ * 32];        // f32 table, correctly rounded
__device__ float g_sin[SEQ * 32];

// ---------------- RoPE table: bit-match the reference's f32 op chain ----------------
// ref: e = arange(0,64,2)/64 (exact); p = 10000**e (f32); invf = 1.0/p (f32 div);
//      ang = pos * invf (f32 mult); cos/sin f32.
// We compute p32 correctly rounded via double pow, reproduce the f32 division and
// f32 multiply exactly, then produce correctly-rounded f32 cos/sin of that f32
// angle via double range reduction.
__global__ void rope_table_kernel() {
    int idx = blockIdx.x * blockDim.x + threadIdx.x;
    if (idx >= SEQ * 32) return;
    int i = idx & 31;
    int pos = idx >> 5;
    float p32 = (float)pow(10000.0, (double)i / 32.0);  // CR f32 of 10000^e
    float invf = 1.0f / p32;                            // f32 division like ref
    float ang = (float)pos * invf;                      // f32 product like ref
    const double TWO_PI = 6.283185307179586476925286766559;
    double dr = (double)ang;
    dr -= TWO_PI * floor(dr / TWO_PI + 0.5);            // exact reduction of f32 angle
    g_cos[idx] = (float)cos(dr);                        // CR f32 cos of the f32 angle
    g_sin[idx] = (float)sin(dr);
}

// ---------------- fp64 NT GEMM (warp per output): C[m][n] = sum_k A[m][k]*B[n][k] ----------------
// f32 inputs, exact f32x f32 products in double, double accumulation -> true dot.
__global__ __launch_bounds__(256) void gemm_warp_d(const float* __restrict__ A,
                                                   const float* __restrict__ B,
                                                   double* __restrict__ C,
                                                   int M, int N, int K) {
    int gw = blockIdx.x * 8 + (threadIdx.x >> 5);
    if (gw >= M * N) return;
    int m = gw / N, n = gw % N;
    int lane = threadIdx.x & 31;
    const float4* a4 = (const float4*)(A + (size_t)m * K);
    const float4* b4 = (const float4*)(B + (size_t)n * K);
    int K4 = K >> 2;
    double acc = 0.0;
    for (int k = lane; k < K4; k += 32) {
        float4 av = a4[k], bv = b4[k];
        acc += (double)av.x * (double)bv.x;
        acc += (double)av.y * (double)bv.y;
        acc += (double)av.z * (double)bv.z;
        acc += (double)av.w * (double)bv.w;
    }
#pragma unroll
    for (int o = 16; o; o >>= 1) acc += __shfl_xor_sync(0xffffffffu, acc, o);
    if (lane == 0) C[(size_t)m * N + n] = acc;
}

// ---------------- fp32 NT GEMM (warp per output) for V and out-proj ----------------
__global__ __launch_bounds__(256) void gemm_warp(const float* __restrict__ A,
                                                 const float* __restrict__ B,
                                                 float* __restrict__ C,
                                                 int M, int N, int K) {
    int gw = blockIdx.x * 8 + (threadIdx.x >> 5);
    if (gw >= M * N) return;
    int m = gw / N, n = gw % N;
    int lane = threadIdx.x & 31;
    const float4* a4 = (const float4*)(A + (size_t)m * K);
    const float4* b4 = (const float4*)(B + (size_t)n * K);
    int K4 = K >> 2;
    float acc = 0.f;
    for (int k = lane; k < K4; k += 32) {
        float4 av = a4[k], bv = b4[k];
        acc += av.x * bv.x + av.y * bv.y + av.z * bv.z + av.w * bv.w;
    }
#pragma unroll
    for (int o = 16; o; o >>= 1) acc += __shfl_xor_sync(0xffffffffu, acc, o);
    if (lane == 0) C[(size_t)m * N + n] = acc;
}

// ---------------- RoPE apply in fp64 (cos/sin widened from the matched f32 table) ----------------
__global__ void rope_kernel_d(double* __restrict__ X, int n_heads) {
    int idx = blockIdx.x * blockDim.x + threadIdx.x;
    int total = SEQ * n_heads * 32;
    if (idx >= total) return;
    int i = idx % 32;
    int h = (idx / 32) % n_heads;
    int pos = idx / (32 * n_heads);
    double c = (double)g_cos[pos * 32 + i];
    double s = (double)g_sin[pos * 32 + i];
    double* row = X + (size_t)pos * (n_heads * DH) + h * DH;
    double x1 = row[i];
    double x2 = row[i + 32];
    row[i]      = x1 * c - x2 * s;
    row[i + 32] = x2 * c + x1 * s;
}

// monotone float->uint map (order-preserving)
__device__ __forceinline__ unsigned fmap(float f) {
    unsigned u = __float_as_uint(f);
    return (u & 0x80000000u) ? ~u : (u | 0x80000000u);
}

// ---------------- attention: one block per (qi, h) ----------------
// scores: fp64 dot of roped q/k, /8 (exact), rounded to f32 (= ref's f32 score
// up to ref's own rounding). Then exact top-64 (ties kept), softmax, AV in f32.
__global__ __launch_bounds__(256) void attn_simple() {
    __shared__ double qd[DH];
    __shared__ float sc[SEQ];              // f32 scores, then weights in place
    __shared__ unsigned rm[SEQ / 32];
    __shared__ unsigned long long wred[8];
    __shared__ float fred[8];
    __shared__ float s_smax, s_den;
    __shared__ unsigned s_thr;
    __shared__ float4 red4[16][16];

    int tid = threadIdx.x, lane = tid & 31, wid = tid >> 5;
    int qi = blockIdx.x, h = blockIdx.y;
    int kvh = h >> 2;
    int len = qi + 1;

    if (tid < DH) qd[tid] = g_Qd[(size_t)qi * (QH * DH) + h * DH + tid];
    for (int i = tid; i < SEQ / 32; i += 256) rm[i] = 0;
    __syncthreads();

    // scores: one warp per key row, fp64 accumulate
    for (int j = wid; j < len; j += 8) {
        const double* kr = g_Kd + (size_t)j * (KVH * DH) + kvh * DH;
        double s = qd[lane] * kr[lane] + qd[lane + 32] * kr[lane + 32];
#pragma unroll
        for (int o = 16; o; o >>= 1) s += __shfl_xor_sync(0xffffffffu, s, o);
        if (lane == 0) sc[j] = (float)(s * 0.125);
    }
    __syncthreads();

    // exact top-k on f32 scores via max extraction; key = (fmap(score) << 11) | j
    int passes = len < TOPK ? len : TOPK;
    for (int p = 0; p < passes; p++) {
        unsigned long long local = 0ull;
        for (int j = tid; j < len; j += 256) {
            if (!((rm[j >> 5] >> (j & 31)) & 1u)) {
                unsigned long long key =
                    ((unsigned long long)fmap(sc[j]) << 11) | (unsigned)j;
                if (key > local) local = key;
            }
        }
#pragma unroll
        for (int o = 16; o; o >>= 1) {
            unsigned long long v = __shfl_xor_sync(0xffffffffu, local, o);
            if (v > local) local = v;
        }
        if (lane == 0) wred[wid] = local;
        __syncthreads();
        if (tid == 0) {
            unsigned long long mx = wred[0];
            for (int w = 1; w < 8; w++)
                if (wred[w] > mx) mx = wred[w];
            int j = (int)(mx & 0x7FFull);
            rm[j >> 5] |= 1u << (j & 31);
            if (p == 0) s_smax = sc[j];
            s_thr = (unsigned)(mx >> 11);
        }
        __syncthreads();
    }
    unsigned thr = (len > TOPK) ? s_thr : 0u;
    float smax = s_smax;

    // weights in place + denominator (deterministic reduction order)
    float part = 0.f;
    __syncthreads();
    for (int j = tid; j < len; j += 256) {
        float v = sc[j];
        float wv = (fmap(v) >= thr) ? expf(v - smax) : 0.f;
        sc[j] = wv;
        part += wv;
    }
#pragma unroll
    for (int o = 16; o; o >>= 1) part += __shfl_xor_sync(0xffffffffu, part, o);
    if (lane == 0) fred[wid] = part;
    __syncthreads();
    if (tid == 0) {
        float d = 0.f;
        for (int w = 0; w < 8; w++) d += fred[w];
        s_den = d;
    }
    __syncthreads();
    float inv = 1.f / s_den;

    // AV: 16 j-groups x 16 float4-dims, deterministic tree
    {
        int g = tid >> 4, d4 = tid & 15;
        float4 a = make_float4(0.f, 0.f, 0.f, 0.f);
        for (int j = g; j < len; j += 16) {
            float wv = sc[j];
            if (wv != 0.f) {
                float4 vv = *((const float4*)(g_V + (size_t)j * (KVH * DH) + kvh * DH) + d4);
                a.x += wv * vv.x; a.y += wv * vv.y;
                a.z += wv * vv.z; a.w += wv * vv.w;
            }
        }
        red4[g][d4] = a;
    }
    __syncthreads();
    if (tid < 16) {
        float4 a = make_float4(0.f, 0.f, 0.f, 0.f);
        for (int g = 0; g < 16; g++) {
            float4 v = red4[g][tid];
            a.x += v.x; a.y += v.y; a.z += v.z; a.w += v.w;
        }
        a.x *= inv; a.y *= inv; a.z *= inv; a.w *= inv;
        *((float4*)(g_AO + (size_t)qi * (QH * DH) + h * DH) + tid) = a;
    }
}

// ---------------- launch ----------------
extern "C" void kernel_launch(void* const* d_in, const int* in_sizes, int n_in,
                              void* d_out, int out_size) {
    (void)out_size;
    // Size-based binding: x unique; (Wq, Wo) big pair in order; (Wk, Wv) small pair.
    int ixv = -1, big[2] = {-1, -1}, sml[2] = {-1, -1};
    int nb = 0, ns = 0;
    for (int i = 0; i < n_in; i++) {
        if (in_sizes[i] == SEQ * DMODEL && ixv < 0) ixv = i;
        else if (in_sizes[i] == QH * DH * DMODEL && nb < 2) big[nb++] = i;
        else if (in_sizes[i] == KVH * DH * DMODEL && ns < 2) sml[ns++] = i;
    }
    if (ixv < 0 || nb < 2 || ns < 2) {  // fallback: dict order
        ixv = 0; big[0] = 1; big[1] = 4; sml[0] = 2; sml[1] = 3;
    }
    const float* x  = (const float*)d_in[ixv];
    const float* Wq = (const float*)d_in[big[0]];
    const float* Wo = (const float*)d_in[big[1]];
    const float* Wk = (const float*)d_in[sml[0]];
    const float* Wv = (const float*)d_in[sml[1]];
    float* out = (float*)d_out;

    double *Qd, *Kd;
    float *V, *AO;
    cudaGetSymbolAddress((void**)&Qd, g_Qd);
    cudaGetSymbolAddress((void**)&Kd, g_Kd);
    cudaGetSymbolAddress((void**)&V, g_V);
    cudaGetSymbolAddress((void**)&AO, g_AO);

    rope_table_kernel<<<(SEQ * 32 + 255) / 256, 256>>>();

    // q, k projections in fp64 (true values); V in fp32
    gemm_warp_d<<<(SEQ * QH * DH + 7) / 8, 256>>>(x, Wq, Qd, SEQ, QH * DH, DMODEL);
    gemm_warp_d<<<(SEQ * KVH * DH + 7) / 8, 256>>>(x, Wk, Kd, SEQ, KVH * DH, DMODEL);
    gemm_warp<<<(SEQ * KVH * DH + 7) / 8, 256>>>(x, Wv, V, SEQ, KVH * DH, DMODEL);

    rope_kernel_d<<<(SEQ * QH * 32) / 256, 256>>>(Qd, QH);
    rope_kernel_d<<<(SEQ * KVH * 32) / 256, 256>>>(Kd, KVH);

    attn_simple<<<dim3(SEQ, QH), 256>>>();

    gemm_warp<<<(SEQ * DMODEL + 7) / 8, 256>>>(AO, Wo, out, SEQ, DMODEL, QH * DH);
}

// round 8
// speedup vs baseline: 7.3761x; 7.3761x over previous
#include <cuda_runtime.h>
#include <math.h>

#define SEQ 2048
#define DMODEL 1024
#define QH 16
#define KVH 4
#define DH 64
#define TOPK 64

// ---------------- scratch (__device__ globals; no allocations) ----------------
__device__ float2 g_Qff[SEQ * QH * DH];   // 16 MB roped q, float-float (hi,lo)
__device__ float2 g_Kff[SEQ * KVH * DH];  // 4 MB  roped k, float-float
__device__ float g_V[SEQ * KVH * DH];     // 2 MB
__device__ float g_AO[SEQ * QH * DH];     // 8 MB
__device__ float g_cos[SEQ * 32];
__device__ float g_sin[SEQ * 32];

// ---------------- float-float primitives ----------------
// acc(h,l) += a*b with exact product (TwoProdFMA) and compensated sum (TwoSum)
__device__ __forceinline__ void ff_mac(float& h, float& l, float a, float b) {
    float p = a * b;
    float e = fmaf(a, b, -p);       // exact product error
    float s = h + p;
    float bb = s - h;
    float err = (h - (s - bb)) + (p - bb);
    h = s;
    l += err + e;
}

// ---------------- RoPE table: bit-match the reference's f32 op chain ----------------
__global__ void rope_table_kernel() {
    int idx = blockIdx.x * blockDim.x + threadIdx.x;
    if (idx >= SEQ * 32) return;
    int i = idx & 31;
    int pos = idx >> 5;
    float p32 = (float)pow(10000.0, (double)i / 32.0);  // CR f32 of 10000^e
    float invf = 1.0f / p32;                            // f32 division like ref
    float ang = (float)pos * invf;                      // f32 product like ref
    const double TWO_PI = 6.283185307179586476925286766559;
    double dr = (double)ang;
    dr -= TWO_PI * floor(dr / TWO_PI + 0.5);            // exact reduction of f32 angle
    g_cos[idx] = (float)cos(dr);
    g_sin[idx] = (float)sin(dr);
}

// ---------------- tiled NT GEMM -> float-float output ----------------
// C[m][n] = sum_k A[m][k]*B[n][k], exact products + compensated accumulation.
__global__ __launch_bounds__(256) void gemm_nt_ff(const float* __restrict__ A,
                                                  const float* __restrict__ B,
                                                  float2* __restrict__ C,
                                                  int M, int N, int K) {
    __shared__ float As[16][68];
    __shared__ float Bs[16][68];
    int bm = blockIdx.y * 64, bn = blockIdx.x * 64;
    int tid = threadIdx.x;
    int tx = tid & 15, ty = tid >> 4;
    float ah[4][4] = {}, al[4][4] = {};
    for (int k0 = 0; k0 < K; k0 += 16) {
#pragma unroll
        for (int t = 0; t < 4; t++) {
            int idx = tid + t * 256;
            int r = idx >> 4, kk = idx & 15;
            As[kk][r] = A[(size_t)(bm + r) * K + k0 + kk];
            Bs[kk][r] = B[(size_t)(bn + r) * K + k0 + kk];
        }
        __syncthreads();
#pragma unroll
        for (int kk = 0; kk < 16; kk++) {
            float a[4], b[4];
#pragma unroll
            for (int i = 0; i < 4; i++) a[i] = As[kk][ty * 4 + i];
#pragma unroll
            for (int j = 0; j < 4; j++) b[j] = Bs[kk][tx * 4 + j];
#pragma unroll
            for (int i = 0; i < 4; i++)
#pragma unroll
                for (int j = 0; j < 4; j++) ff_mac(ah[i][j], al[i][j], a[i], b[j]);
        }
        __syncthreads();
    }
#pragma unroll
    for (int i = 0; i < 4; i++)
#pragma unroll
        for (int j = 0; j < 4; j++) {
            float hh = ah[i][j] + al[i][j];               // renormalize
            float ll = al[i][j] - (hh - ah[i][j]);
            C[(size_t)(bm + ty * 4 + i) * N + bn + tx * 4 + j] = make_float2(hh, ll);
        }
}

// ---------------- tiled NT GEMM fp32 (V proj, out proj) ----------------
__global__ __launch_bounds__(256) void gemm_nt(const float* __restrict__ A,
                                               const float* __restrict__ B,
                                               float* __restrict__ C,
                                               int M, int N, int K) {
    __shared__ float As[16][68];
    __shared__ float Bs[16][68];
    int bm = blockIdx.y * 64, bn = blockIdx.x * 64;
    int tid = threadIdx.x;
    int tx = tid & 15, ty = tid >> 4;
    float acc[4][4] = {};
    for (int k0 = 0; k0 < K; k0 += 16) {
#pragma unroll
        for (int t = 0; t < 4; t++) {
            int idx = tid + t * 256;
            int r = idx >> 4, kk = idx & 15;
            As[kk][r] = A[(size_t)(bm + r) * K + k0 + kk];
            Bs[kk][r] = B[(size_t)(bn + r) * K + k0 + kk];
        }
        __syncthreads();
#pragma unroll
        for (int kk = 0; kk < 16; kk++) {
            float a[4], b[4];
#pragma unroll
            for (int i = 0; i < 4; i++) a[i] = As[kk][ty * 4 + i];
#pragma unroll
            for (int j = 0; j < 4; j++) b[j] = Bs[kk][tx * 4 + j];
#pragma unroll
            for (int i = 0; i < 4; i++)
#pragma unroll
                for (int j = 0; j < 4; j++) acc[i][j] += a[i] * b[j];
        }
        __syncthreads();
    }
#pragma unroll
    for (int i = 0; i < 4; i++)
#pragma unroll
        for (int j = 0; j < 4; j++)
            C[(size_t)(bm + ty * 4 + i) * N + bn + tx * 4 + j] = acc[i][j];
}

// ---------------- RoPE apply on float-float arrays (rotation in fp64, cheap) ----------------
__global__ void rope_ff(float2* __restrict__ X, int n_heads) {
    int idx = blockIdx.x * blockDim.x + threadIdx.x;
    int total = SEQ * n_heads * 32;
    if (idx >= total) return;
    int i = idx % 32;
    int h = (idx / 32) % n_heads;
    int pos = idx / (32 * n_heads);
    double c = (double)g_cos[pos * 32 + i];
    double s = (double)g_sin[pos * 32 + i];
    float2* row = X + (size_t)pos * (n_heads * DH) + h * DH;
    double x1 = (double)row[i].x + (double)row[i].y;
    double x2 = (double)row[i + 32].x + (double)row[i + 32].y;
    double r1 = x1 * c - x2 * s;
    double r2 = x2 * c + x1 * s;
    float h1 = (float)r1, h2 = (float)r2;
    row[i]      = make_float2(h1, (float)(r1 - (double)h1));
    row[i + 32] = make_float2(h2, (float)(r2 - (double)h2));
}

// monotone float->uint map (order-preserving)
__device__ __forceinline__ unsigned fmap(float f) {
    unsigned u = __float_as_uint(f);
    return (u & 0x80000000u) ? ~u : (u | 0x80000000u);
}

// ---------------- attention: one block per (qi, h) ----------------
// scores: float-float dot of roped ff q/k -> f32 (fp64-class accuracy).
// selection: 2-level 11-bit radix descent + exact extraction in residual class.
__global__ __launch_bounds__(256) void attn_fast() {
    __shared__ float2 q2[DH];
    __shared__ float sc[SEQ];
    __shared__ int hist[2048];
    __shared__ int psum[256];
    __shared__ unsigned long long buf[256];
    __shared__ unsigned bufrm[8];
    __shared__ unsigned long long wred[8];
    __shared__ unsigned long long s_mx;
    __shared__ float fred[8];
    __shared__ float s_smax, s_den;
    __shared__ unsigned s_thr;
    __shared__ int s_b, s_k, s_cnt;
    __shared__ float4 red4[16][16];

    int tid = threadIdx.x, lane = tid & 31, wid = tid >> 5;
    int qi = blockIdx.x, h = blockIdx.y;
    int kvh = h >> 2;
    int len = qi + 1;

    if (tid < DH) q2[tid] = g_Qff[(size_t)qi * (QH * DH) + h * DH + tid];
    __syncthreads();

    // ---- scores: one warp per key row, float-float accumulation ----
    for (int j = wid; j < len; j += 8) {
        const float2* kr = g_Kff + (size_t)j * (KVH * DH) + kvh * DH;
        float2 k1 = kr[lane], k2 = kr[lane + 32];
        float2 qa = q2[lane], qb = q2[lane + 32];
        float sh = 0.f, sl = 0.f;
        ff_mac(sh, sl, qa.x, k1.x);
        sl += qa.x * k1.y + qa.y * k1.x;
        ff_mac(sh, sl, qb.x, k2.x);
        sl += qb.x * k2.y + qb.y * k2.x;
#pragma unroll
        for (int o = 16; o; o >>= 1) {
            float oh = __shfl_xor_sync(0xffffffffu, sh, o);
            float ol = __shfl_xor_sync(0xffffffffu, sl, o);
            float s = sh + oh;
            float bb = s - sh;
            float err = (sh - (s - bb)) + (oh - bb);
            sh = s;
            sl += ol + err;
        }
        if (lane == 0) sc[j] = (sh + sl) * 0.125f;
    }
    __syncthreads();

    // ---- row max ----
    {
        float lm = -INFINITY;
        for (int j = tid; j < len; j += 256) lm = fmaxf(lm, sc[j]);
#pragma unroll
        for (int o = 16; o; o >>= 1) lm = fmaxf(lm, __shfl_xor_sync(0xffffffffu, lm, o));
        if (lane == 0) fred[wid] = lm;
        __syncthreads();
        if (tid == 0) {
            float mm = fred[0];
            for (int w = 1; w < 8; w++) mm = fmaxf(mm, fred[w]);
            s_smax = mm;
        }
        __syncthreads();
    }
    float smax = s_smax;

    // ---- exact 64th-largest threshold ----
    unsigned thr = 0;
    if (len > TOPK) {
        // level 1: bins = top 11 bits of u
        for (int i = tid; i < 2048; i += 256) hist[i] = 0;
        __syncthreads();
        for (int j = tid; j < len; j += 256)
            atomicAdd(&hist[fmap(sc[j]) >> 21], 1);
        __syncthreads();
        {
            int cs = 0;
#pragma unroll
            for (int b = 0; b < 8; b++) cs += hist[tid * 8 + b];
            psum[tid] = cs;
        }
        __syncthreads();
        if (tid == 0) {
            int kneed = TOPK, cum = 0, chunk = 0;
            for (int t = 255; t >= 0; t--) {
                if (cum + psum[t] >= kneed) { chunk = t; break; }
                cum += psum[t];
            }
            int b = chunk * 8;
            for (int bb = chunk * 8 + 7; bb >= chunk * 8; bb--) {
                if (cum + hist[bb] >= kneed) { b = bb; break; }
                cum += hist[bb];
            }
            s_b = b;
            s_k = kneed - cum;
        }
        __syncthreads();
        int b1 = s_b, k1 = s_k;

        // level 2: within bin b1, bins = next 11 bits
        for (int i = tid; i < 2048; i += 256) hist[i] = 0;
        __syncthreads();
        for (int j = tid; j < len; j += 256) {
            unsigned u = fmap(sc[j]);
            if ((int)(u >> 21) == b1) atomicAdd(&hist[(u >> 10) & 0x7FF], 1);
        }
        __syncthreads();
        {
            int cs = 0;
#pragma unroll
            for (int b = 0; b < 8; b++) cs += hist[tid * 8 + b];
            psum[tid] = cs;
        }
        __syncthreads();
        if (tid == 0) {
            int kneed = k1, cum = 0, chunk = 0;
            for (int t = 255; t >= 0; t--) {
                if (cum + psum[t] >= kneed) { chunk = t; break; }
                cum += psum[t];
            }
            int b = chunk * 8;
            for (int bb = chunk * 8 + 7; bb >= chunk * 8; bb--) {
                if (cum + hist[bb] >= kneed) { b = bb; break; }
                cum += hist[bb];
            }
            s_b = b;
            s_k = kneed - cum;
            s_cnt = 0;
        }
        __syncthreads();
        int b2 = s_b, k2 = s_k;
        unsigned pref = ((unsigned)b1 << 11) | (unsigned)b2;

        // gather the residual class
        if (tid < 8) bufrm[tid] = 0;
        __syncthreads();
        for (int j = tid; j < len; j += 256) {
            unsigned u = fmap(sc[j]);
            if ((u >> 10) == pref) {
                int p = atomicAdd(&s_cnt, 1);
                if (p < 256) buf[p] = ((unsigned long long)u << 11) | (unsigned)j;
            }
        }
        __syncthreads();
        int cnt = s_cnt;

        if (cnt <= 256) {
            // extraction of k2-th largest within class (usually k2 == 1)
            for (int p = 0; p < k2; p++) {
                unsigned long long my = 0ull;
                if (tid < cnt && !((bufrm[tid >> 5] >> (tid & 31)) & 1u)) my = buf[tid];
                unsigned long long v = my;
#pragma unroll
                for (int o = 16; o; o >>= 1) {
                    unsigned long long t = __shfl_xor_sync(0xffffffffu, v, o);
                    if (t > v) v = t;
                }
                if (lane == 0) wred[wid] = v;
                __syncthreads();
                if (tid == 0) {
                    unsigned long long mx = wred[0];
                    for (int w = 1; w < 8; w++)
                        if (wred[w] > mx) mx = wred[w];
                    s_mx = mx;
                    if (p == k2 - 1) s_thr = (unsigned)(mx >> 11);
                }
                __syncthreads();
                if (my == s_mx && my != 0ull) bufrm[tid >> 5] |= 1u << (tid & 31);
                __syncthreads();
            }
        } else {
            // fallback: full-row extraction (round-7 verified path), rm in hist
            for (int i = tid; i < 64; i += 256) hist[i] = 0;
            __syncthreads();
            unsigned* rm = (unsigned*)hist;
            for (int p = 0; p < TOPK; p++) {
                unsigned long long local = 0ull;
                for (int j = tid; j < len; j += 256) {
                    if (!((rm[j >> 5] >> (j & 31)) & 1u)) {
                        unsigned long long key =
                            ((unsigned long long)fmap(sc[j]) << 11) | (unsigned)j;
                        if (key > local) local = key;
                    }
                }
#pragma unroll
                for (int o = 16; o; o >>= 1) {
                    unsigned long long t = __shfl_xor_sync(0xffffffffu, local, o);
                    if (t > local) local = t;
                }
                if (lane == 0) wred[wid] = local;
                __syncthreads();
                if (tid == 0) {
                    unsigned long long mx = wred[0];
                    for (int w = 1; w < 8; w++)
                        if (wred[w] > mx) mx = wred[w];
                    int j = (int)(mx & 0x7FFull);
                    rm[j >> 5] |= 1u << (j & 31);
                    if (p == TOPK - 1) s_thr = (unsigned)(mx >> 11);
                }
                __syncthreads();
            }
        }
        thr = s_thr;
    }

    // ---- weights + denominator (deterministic reduction order) ----
    float part = 0.f;
    __syncthreads();
    for (int j = tid; j < len; j += 256) {
        float v = sc[j];
        float wv = (fmap(v) >= thr) ? expf(v - smax) : 0.f;
        sc[j] = wv;
        part += wv;
    }
#pragma unroll
    for (int o = 16; o; o >>= 1) part += __shfl_xor_sync(0xffffffffu, part, o);
    if (lane == 0) fred[wid] = part;
    __syncthreads();
    if (tid == 0) {
        float d = 0.f;
        for (int w = 0; w < 8; w++) d += fred[w];
        s_den = d;
    }
    __syncthreads();
    float inv = 1.f / s_den;

    // ---- AV: 16 j-groups x 16 float4-dims, deterministic tree ----
    {
        int g = tid >> 4, d4 = tid & 15;
        float4 a = make_float4(0.f, 0.f, 0.f, 0.f);
        for (int j = g; j < len; j += 16) {
            float wv = sc[j];
            if (wv != 0.f) {
                float4 vv = *((const float4*)(g_V + (size_t)j * (KVH * DH) + kvh * DH) + d4);
                a.x += wv * vv.x; a.y += wv * vv.y;
                a.z += wv * vv.z; a.w += wv * vv.w;
            }
        }
        red4[g][d4] = a;
    }
    __syncthreads();
    if (tid < 16) {
        float4 a = make_float4(0.f, 0.f, 0.f, 0.f);
        for (int g = 0; g < 16; g++) {
            float4 v = red4[g][tid];
            a.x += v.x; a.y += v.y; a.z += v.z; a.w += v.w;
        }
        a.x *= inv; a.y *= inv; a.z *= inv; a.w *= inv;
        *((float4*)(g_AO + (size_t)qi * (QH * DH) + h * DH) + tid) = a;
    }
}

// ---------------- launch ----------------
extern "C" void kernel_launch(void* const* d_in, const int* in_sizes, int n_in,
                              void* d_out, int out_size) {
    (void)out_size;
    int ixv = -1, big[2] = {-1, -1}, sml[2] = {-1, -1};
    int nb = 0, ns = 0;
    for (int i = 0; i < n_in; i++) {
        if (in_sizes[i] == SEQ * DMODEL && ixv < 0) ixv = i;
        else if (in_sizes[i] == QH * DH * DMODEL && nb < 2) big[nb++] = i;
        else if (in_sizes[i] == KVH * DH * DMODEL && ns < 2) sml[ns++] = i;
    }
    if (ixv < 0 || nb < 2 || ns < 2) {
        ixv = 0; big[0] = 1; big[1] = 4; sml[0] = 2; sml[1] = 3;
    }
    const float* x  = (const float*)d_in[ixv];
    const float* Wq = (const float*)d_in[big[0]];
    const float* Wo = (const float*)d_in[big[1]];
    const float* Wk = (const float*)d_in[sml[0]];
    const float* Wv = (const float*)d_in[sml[1]];
    float* out = (float*)d_out;

    float2 *Qff, *Kff;
    float *V, *AO;
    cudaGetSymbolAddress((void**)&Qff, g_Qff);
    cudaGetSymbolAddress((void**)&Kff, g_Kff);
    cudaGetSymbolAddress((void**)&V, g_V);
    cudaGetSymbolAddress((void**)&AO, g_AO);

    rope_table_kernel<<<(SEQ * 32 + 255) / 256, 256>>>();

    // q, k projections in float-float; V in fp32
    gemm_nt_ff<<<dim3((QH * DH) / 64, SEQ / 64), 256>>>(x, Wq, Qff, SEQ, QH * DH, DMODEL);
    gemm_nt_ff<<<dim3((KVH * DH) / 64, SEQ / 64), 256>>>(x, Wk, Kff, SEQ, KVH * DH, DMODEL);
    gemm_nt<<<dim3((KVH * DH) / 64, SEQ / 64), 256>>>(x, Wv, V, SEQ, KVH * DH, DMODEL);

    rope_ff<<<(SEQ * QH * 32) / 256, 256>>>(Qff, QH);
    rope_ff<<<(SEQ * KVH * 32) / 256, 256>>>(Kff, KVH);

    attn_fast<<<dim3(SEQ, QH), 256>>>();

    gemm_nt<<<dim3(DMODEL / 64, SEQ / 64), 256>>>(AO, Wo, out, SEQ, DMODEL, QH * DH);
}

// round 9
// speedup vs baseline: 10.8252x; 1.4676x over previous
#include <cuda_runtime.h>
#include <math.h>

#define SEQ 2048
#define DMODEL 1024
#define QH 16
#define KVH 4
#define DH 64
#define TOPK 64

// ---------------- scratch (__device__ globals; no allocations) ----------------
__device__ float2 g_Qff[SEQ * QH * DH];   // 16 MB roped q, float-float (hi,lo)
__device__ float2 g_Kff[SEQ * KVH * DH];  // 4 MB  roped k, float-float
__device__ float g_V[SEQ * KVH * DH];     // 2 MB
__device__ float g_AO[SEQ * QH * DH];     // 8 MB
__device__ float g_S[SEQ * SEQ];          // 16 MB per-head score scratch
__device__ float g_cos[SEQ * 32];
__device__ float g_sin[SEQ * 32];

// ---------------- float-float primitives ----------------
__device__ __forceinline__ void ff_mac(float& h, float& l, float a, float b) {
    float p = a * b;
    float e = fmaf(a, b, -p);       // exact product error
    float s = h + p;
    float bb = s - h;
    float err = (h - (s - bb)) + (p - bb);
    h = s;
    l += err + e;
}

// ---------------- RoPE table: bit-match the reference's f32 op chain ----------------
__global__ void rope_table_kernel() {
    int idx = blockIdx.x * blockDim.x + threadIdx.x;
    if (idx >= SEQ * 32) return;
    int i = idx & 31;
    int pos = idx >> 5;
    float p32 = (float)pow(10000.0, (double)i / 32.0);  // CR f32 of 10000^e
    float invf = 1.0f / p32;                            // f32 division like ref
    float ang = (float)pos * invf;                      // f32 product like ref
    const double TWO_PI = 6.283185307179586476925286766559;
    double dr = (double)ang;
    dr -= TWO_PI * floor(dr / TWO_PI + 0.5);            // exact reduction of f32 angle
    g_cos[idx] = (float)cos(dr);
    g_sin[idx] = (float)sin(dr);
}

// ---------------- tiled NT GEMM -> float-float output (Q,K projections) ----------------
__global__ __launch_bounds__(256) void gemm_nt_ff(const float* __restrict__ A,
                                                  const float* __restrict__ B,
                                                  float2* __restrict__ C,
                                                  int M, int N, int K) {
    __shared__ float As[16][68];
    __shared__ float Bs[16][68];
    int bm = blockIdx.y * 64, bn = blockIdx.x * 64;
    int tid = threadIdx.x;
    int tx = tid & 15, ty = tid >> 4;
    float ah[4][4] = {}, al[4][4] = {};
    for (int k0 = 0; k0 < K; k0 += 16) {
#pragma unroll
        for (int t = 0; t < 4; t++) {
            int idx = tid + t * 256;
            int r = idx >> 4, kk = idx & 15;
            As[kk][r] = A[(size_t)(bm + r) * K + k0 + kk];
            Bs[kk][r] = B[(size_t)(bn + r) * K + k0 + kk];
        }
        __syncthreads();
#pragma unroll
        for (int kk = 0; kk < 16; kk++) {
            float a[4], b[4];
#pragma unroll
            for (int i = 0; i < 4; i++) a[i] = As[kk][ty * 4 + i];
#pragma unroll
            for (int j = 0; j < 4; j++) b[j] = Bs[kk][tx * 4 + j];
#pragma unroll
            for (int i = 0; i < 4; i++)
#pragma unroll
                for (int j = 0; j < 4; j++) ff_mac(ah[i][j], al[i][j], a[i], b[j]);
        }
        __syncthreads();
    }
#pragma unroll
    for (int i = 0; i < 4; i++)
#pragma unroll
        for (int j = 0; j < 4; j++) {
            float hh = ah[i][j] + al[i][j];               // renormalize
            float ll = al[i][j] - (hh - ah[i][j]);
            C[(size_t)(bm + ty * 4 + i) * N + bn + tx * 4 + j] = make_float2(hh, ll);
        }
}

// ---------------- tiled NT GEMM fp32 (V proj, out proj) ----------------
__global__ __launch_bounds__(256) void gemm_nt(const float* __restrict__ A,
                                               const float* __restrict__ B,
                                               float* __restrict__ C,
                                               int M, int N, int K) {
    __shared__ float As[16][68];
    __shared__ float Bs[16][68];
    int bm = blockIdx.y * 64, bn = blockIdx.x * 64;
    int tid = threadIdx.x;
    int tx = tid & 15, ty = tid >> 4;
    float acc[4][4] = {};
    for (int k0 = 0; k0 < K; k0 += 16) {
#pragma unroll
        for (int t = 0; t < 4; t++) {
            int idx = tid + t * 256;
            int r = idx >> 4, kk = idx & 15;
            As[kk][r] = A[(size_t)(bm + r) * K + k0 + kk];
            Bs[kk][r] = B[(size_t)(bn + r) * K + k0 + kk];
        }
        __syncthreads();
#pragma unroll
        for (int kk = 0; kk < 16; kk++) {
            float a[4], b[4];
#pragma unroll
            for (int i = 0; i < 4; i++) a[i] = As[kk][ty * 4 + i];
#pragma unroll
            for (int j = 0; j < 4; j++) b[j] = Bs[kk][tx * 4 + j];
#pragma unroll
            for (int i = 0; i < 4; i++)
#pragma unroll
                for (int j = 0; j < 4; j++) acc[i][j] += a[i] * b[j];
        }
        __syncthreads();
    }
#pragma unroll
    for (int i = 0; i < 4; i++)
#pragma unroll
        for (int j = 0; j < 4; j++)
            C[(size_t)(bm + ty * 4 + i) * N + bn + tx * 4 + j] = acc[i][j];
}

// ---------------- RoPE apply on float-float arrays ----------------
__global__ void rope_ff(float2* __restrict__ X, int n_heads) {
    int idx = blockIdx.x * blockDim.x + threadIdx.x;
    int total = SEQ * n_heads * 32;
    if (idx >= total) return;
    int i = idx % 32;
    int h = (idx / 32) % n_heads;
    int pos = idx / (32 * n_heads);
    double c = (double)g_cos[pos * 32 + i];
    double s = (double)g_sin[pos * 32 + i];
    float2* row = X + (size_t)pos * (n_heads * DH) + h * DH;
    double x1 = (double)row[i].x + (double)row[i].y;
    double x2 = (double)row[i + 32].x + (double)row[i + 32].y;
    double r1 = x1 * c - x2 * s;
    double r2 = x2 * c + x1 * s;
    float h1 = (float)r1, h2 = (float)r2;
    row[i]      = make_float2(h1, (float)(r1 - (double)h1));
    row[i + 32] = make_float2(h2, (float)(r2 - (double)h2));
}

// monotone float->uint map (order-preserving)
__device__ __forceinline__ unsigned fmap(float f) {
    unsigned u = __float_as_uint(f);
    return (u & 0x80000000u) ? ~u : (u | 0x80000000u);
}

// ---------------- score GEMM (ff): 64x64 tile of S = Q_h K_h^T / 8, lower triangle ----------------
// dynamic smem: Qh/Ql/Kh/Kl each [64][65] floats = 66560 B total
__global__ __launch_bounds__(256) void score_ff(int h) {
    extern __shared__ float sm[];
    float (*Qh)[65] = (float(*)[65])sm;
    float (*Ql)[65] = (float(*)[65])(sm + 4160);
    float (*Kh)[65] = (float(*)[65])(sm + 8320);
    float (*Kl)[65] = (float(*)[65])(sm + 12480);
    int tid = threadIdx.x;
    int t = blockIdx.x;
    int bi = (int)((sqrtf(8.0f * (float)t + 1.0f) - 1.0f) * 0.5f);
    while ((bi + 1) * (bi + 2) / 2 <= t) bi++;
    while (bi * (bi + 1) / 2 > t) bi--;
    int bj = t - bi * (bi + 1) / 2;
    int qi0 = bi * 64, j0 = bj * 64;
    int kvh = h >> 2;

    // load tiles transposed: [dim][row]
#pragma unroll
    for (int p = 0; p < 16; p++) {
        int idx = tid + p * 256;
        int d = idx & 63, r = idx >> 6;
        float2 v = g_Qff[(size_t)(qi0 + r) * (QH * DH) + h * DH + d];
        Qh[d][r] = v.x; Ql[d][r] = v.y;
        float2 w = g_Kff[(size_t)(j0 + r) * (KVH * DH) + kvh * DH + d];
        Kh[d][r] = w.x; Kl[d][r] = w.y;
    }
    __syncthreads();

    int tx = tid & 15, ty = tid >> 4;   // cols tx+16j, rows ty+16i (conflict-free)
    float ah[4][4] = {}, al[4][4] = {};
#pragma unroll 4
    for (int kk = 0; kk < 64; kk++) {
        float qh_[4], ql_[4], kh_[4], kl_[4];
#pragma unroll
        for (int i = 0; i < 4; i++) { qh_[i] = Qh[kk][ty + 16 * i]; ql_[i] = Ql[kk][ty + 16 * i]; }
#pragma unroll
        for (int j = 0; j < 4; j++) { kh_[j] = Kh[kk][tx + 16 * j]; kl_[j] = Kl[kk][tx + 16 * j]; }
#pragma unroll
        for (int i = 0; i < 4; i++)
#pragma unroll
            for (int j = 0; j < 4; j++) {
                ff_mac(ah[i][j], al[i][j], qh_[i], kh_[j]);
                al[i][j] += qh_[i] * kl_[j] + ql_[i] * kh_[j];
            }
    }
#pragma unroll
    for (int i = 0; i < 4; i++) {
        int qi = qi0 + ty + 16 * i;
#pragma unroll
        for (int j = 0; j < 4; j++) {
            int jj = j0 + tx + 16 * j;
            if (jj <= qi)
                g_S[(size_t)qi * SEQ + jj] = (ah[i][j] + al[i][j]) * 0.125f;
        }
    }
}

// ---------------- attention phase B: one block per query row (head h) ----------------
// round-8 validated machinery; scores read from g_S instead of computed in-block.
__global__ __launch_bounds__(256) void attn_row(int h) {
    __shared__ float sc[SEQ];
    __shared__ int hist[2048];
    __shared__ int psum[256];
    __shared__ unsigned long long buf[256];
    __shared__ unsigned bufrm[8];
    __shared__ unsigned long long wred[8];
    __shared__ unsigned long long s_mx;
    __shared__ float fred[8];
    __shared__ float s_smax, s_den;
    __shared__ unsigned s_thr;
    __shared__ int s_b, s_k, s_cnt;
    __shared__ float4 red4[16][16];

    int tid = threadIdx.x, lane = tid & 31, wid = tid >> 5;
    int qi = blockIdx.x;
    int kvh = h >> 2;
    int len = qi + 1;

    const float* Srow = g_S + (size_t)qi * SEQ;
    for (int j = tid; j < len; j += 256) sc[j] = Srow[j];
    __syncthreads();

    // ---- row max ----
    {
        float lm = -INFINITY;
        for (int j = tid; j < len; j += 256) lm = fmaxf(lm, sc[j]);
#pragma unroll
        for (int o = 16; o; o >>= 1) lm = fmaxf(lm, __shfl_xor_sync(0xffffffffu, lm, o));
        if (lane == 0) fred[wid] = lm;
        __syncthreads();
        if (tid == 0) {
            float mm = fred[0];
            for (int w = 1; w < 8; w++) mm = fmaxf(mm, fred[w]);
            s_smax = mm;
        }
        __syncthreads();
    }
    float smax = s_smax;

    // ---- exact 64th-largest threshold ----
    unsigned thr = 0;
    if (len > TOPK) {
        for (int i = tid; i < 2048; i += 256) hist[i] = 0;
        __syncthreads();
        for (int j = tid; j < len; j += 256)
            atomicAdd(&hist[fmap(sc[j]) >> 21], 1);
        __syncthreads();
        {
            int cs = 0;
#pragma unroll
            for (int b = 0; b < 8; b++) cs += hist[tid * 8 + b];
            psum[tid] = cs;
        }
        __syncthreads();
        if (tid == 0) {
            int kneed = TOPK, cum = 0, chunk = 0;
            for (int t = 255; t >= 0; t--) {
                if (cum + psum[t] >= kneed) { chunk = t; break; }
                cum += psum[t];
            }
            int b = chunk * 8;
            for (int bb = chunk * 8 + 7; bb >= chunk * 8; bb--) {
                if (cum + hist[bb] >= kneed) { b = bb; break; }
                cum += hist[bb];
            }
            s_b = b;
            s_k = kneed - cum;
        }
        __syncthreads();
        int b1 = s_b, k1 = s_k;

        for (int i = tid; i < 2048; i += 256) hist[i] = 0;
        __syncthreads();
        for (int j = tid; j < len; j += 256) {
            unsigned u = fmap(sc[j]);
            if ((int)(u >> 21) == b1) atomicAdd(&hist[(u >> 10) & 0x7FF], 1);
        }
        __syncthreads();
        {
            int cs = 0;
#pragma unroll
            for (int b = 0; b < 8; b++) cs += hist[tid * 8 + b];
            psum[tid] = cs;
        }
        __syncthreads();
        if (tid == 0) {
            int kneed = k1, cum = 0, chunk = 0;
            for (int t = 255; t >= 0; t--) {
                if (cum + psum[t] >= kneed) { chunk = t; break; }
                cum += psum[t];
            }
            int b = chunk * 8;
            for (int bb = chunk * 8 + 7; bb >= chunk * 8; bb--) {
                if (cum + hist[bb] >= kneed) { b = bb; break; }
                cum += hist[bb];
            }
            s_b = b;
            s_k = kneed - cum;
            s_cnt = 0;
        }
        __syncthreads();
        int b2 = s_b, k2 = s_k;
        unsigned pref = ((unsigned)b1 << 11) | (unsigned)b2;

        if (tid < 8) bufrm[tid] = 0;
        __syncthreads();
        for (int j = tid; j < len; j += 256) {
            unsigned u = fmap(sc[j]);
            if ((u >> 10) == pref) {
                int p = atomicAdd(&s_cnt, 1);
                if (p < 256) buf[p] = ((unsigned long long)u << 11) | (unsigned)j;
            }
        }
        __syncthreads();
        int cnt = s_cnt;

        if (cnt <= 256) {
            for (int p = 0; p < k2; p++) {
                unsigned long long my = 0ull;
                if (tid < cnt && !((bufrm[tid >> 5] >> (tid & 31)) & 1u)) my = buf[tid];
                unsigned long long v = my;
#pragma unroll
                for (int o = 16; o; o >>= 1) {
                    unsigned long long t = __shfl_xor_sync(0xffffffffu, v, o);
                    if (t > v) v = t;
                }
                if (lane == 0) wred[wid] = v;
                __syncthreads();
                if (tid == 0) {
                    unsigned long long mx = wred[0];
                    for (int w = 1; w < 8; w++)
                        if (wred[w] > mx) mx = wred[w];
                    s_mx = mx;
                    if (p == k2 - 1) s_thr = (unsigned)(mx >> 11);
                }
                __syncthreads();
                if (my == s_mx && my != 0ull) bufrm[tid >> 5] |= 1u << (tid & 31);
                __syncthreads();
            }
        } else {
            for (int i = tid; i < 64; i += 256) hist[i] = 0;
            __syncthreads();
            unsigned* rm = (unsigned*)hist;
            for (int p = 0; p < TOPK; p++) {
                unsigned long long local = 0ull;
                for (int j = tid; j < len; j += 256) {
                    if (!((rm[j >> 5] >> (j & 31)) & 1u)) {
                        unsigned long long key =
                            ((unsigned long long)fmap(sc[j]) << 11) | (unsigned)j;
                        if (key > local) local = key;
                    }
                }
#pragma unroll
                for (int o = 16; o; o >>= 1) {
                    unsigned long long t = __shfl_xor_sync(0xffffffffu, local, o);
                    if (t > local) local = t;
                }
                if (lane == 0) wred[wid] = local;
                __syncthreads();
                if (tid == 0) {
                    unsigned long long mx = wred[0];
                    for (int w = 1; w < 8; w++)
                        if (wred[w] > mx) mx = wred[w];
                    int j = (int)(mx & 0x7FFull);
                    rm[j >> 5] |= 1u << (j & 31);
                    if (p == TOPK - 1) s_thr = (unsigned)(mx >> 11);
                }
                __syncthreads();
            }
        }
        thr = s_thr;
    }

    // ---- weights + denominator (deterministic reduction order) ----
    float part = 0.f;
    __syncthreads();
    for (int j = tid; j < len; j += 256) {
        float v = sc[j];
        float wv = (fmap(v) >= thr) ? expf(v - smax) : 0.f;
        sc[j] = wv;
        part += wv;
    }
#pragma unroll
    for (int o = 16; o; o >>= 1) part += __shfl_xor_sync(0xffffffffu, part, o);
    if (lane == 0) fred[wid] = part;
    __syncthreads();
    if (tid == 0) {
        float d = 0.f;
        for (int w = 0; w < 8; w++) d += fred[w];
        s_den = d;
    }
    __syncthreads();
    float inv = 1.f / s_den;

    // ---- AV: 16 j-groups x 16 float4-dims, deterministic tree ----
    {
        int g = tid >> 4, d4 = tid & 15;
        float4 a = make_float4(0.f, 0.f, 0.f, 0.f);
        for (int j = g; j < len; j += 16) {
            float wv = sc[j];
            if (wv != 0.f) {
                float4 vv = *((const float4*)(g_V + (size_t)j * (KVH * DH) + kvh * DH) + d4);
                a.x += wv * vv.x; a.y += wv * vv.y;
                a.z += wv * vv.z; a.w += wv * vv.w;
            }
        }
        red4[g][d4] = a;
    }
    __syncthreads();
    if (tid < 16) {
        float4 a = make_float4(0.f, 0.f, 0.f, 0.f);
        for (int g = 0; g < 16; g++) {
            float4 v = red4[g][tid];
            a.x += v.x; a.y += v.y; a.z += v.z; a.w += v.w;
        }
        a.x *= inv; a.y *= inv; a.z *= inv; a.w *= inv;
        *((float4*)(g_AO + (size_t)blockIdx.x * (QH * DH) + h * DH) + tid) = a;
    }
}

// ---------------- launch ----------------
extern "C" void kernel_launch(void* const* d_in, const int* in_sizes, int n_in,
                              void* d_out, int out_size) {
    (void)out_size;
    int ixv = -1, big[2] = {-1, -1}, sml[2] = {-1, -1};
    int nb = 0, ns = 0;
    for (int i = 0; i < n_in; i++) {
        if (in_sizes[i] == SEQ * DMODEL && ixv < 0) ixv = i;
        else if (in_sizes[i] == QH * DH * DMODEL && nb < 2) big[nb++] = i;
        else if (in_sizes[i] == KVH * DH * DMODEL && ns < 2) sml[ns++] = i;
    }
    if (ixv < 0 || nb < 2 || ns < 2) {
        ixv = 0; big[0] = 1; big[1] = 4; sml[0] = 2; sml[1] = 3;
    }
    const float* x  = (const float*)d_in[ixv];
    const float* Wq = (const float*)d_in[big[0]];
    const float* Wo = (const float*)d_in[big[1]];
    const float* Wk = (const float*)d_in[sml[0]];
    const float* Wv = (const float*)d_in[sml[1]];
    float* out = (float*)d_out;

    float2 *Qff, *Kff;
    float *V, *AO;
    cudaGetSymbolAddress((void**)&Qff, g_Qff);
    cudaGetSymbolAddress((void**)&Kff, g_Kff);
    cudaGetSymbolAddress((void**)&V, g_V);
    cudaGetSymbolAddress((void**)&AO, g_AO);

    static int smem_set = 0;
    if (!smem_set) {
        cudaFuncSetAttribute(score_ff, cudaFuncAttributeMaxDynamicSharedMemorySize, 66560);
        smem_set = 1;
    }

    rope_table_kernel<<<(SEQ * 32 + 255) / 256, 256>>>();

    gemm_nt_ff<<<dim3((QH * DH) / 64, SEQ / 64), 256>>>(x, Wq, Qff, SEQ, QH * DH, DMODEL);
    gemm_nt_ff<<<dim3((KVH * DH) / 64, SEQ / 64), 256>>>(x, Wk, Kff, SEQ, KVH * DH, DMODEL);
    gemm_nt<<<dim3((KVH * DH) / 64, SEQ / 64), 256>>>(x, Wv, V, SEQ, KVH * DH, DMODEL);

    rope_ff<<<(SEQ * QH * 32) / 256, 256>>>(Qff, QH);
    rope_ff<<<(SEQ * KVH * 32) / 256, 256>>>(Kff, KVH);

    for (int h = 0; h < QH; h++) {
        score_ff<<<(SEQ / 64) * (SEQ / 64 + 1) / 2, 256, 66560>>>(h);
        attn_row<<<SEQ, 256>>>(h);
    }

    gemm_nt<<<dim3(DMODEL / 64, SEQ / 64), 256>>>(AO, Wo, out, SEQ, DMODEL, QH * DH);
}

// round 10
// speedup vs baseline: 11.9923x; 1.1078x over previous
#include <cuda_runtime.h>
#include <math.h>

#define SEQ 2048
#define DMODEL 1024
#define QH 16
#define KVH 4
#define DH 64
#define TOPK 64

// ---------------- scratch (__device__ globals; no allocations) ----------------
__device__ float2 g_Qff[SEQ * QH * DH];            // 16 MB roped q, float-float
__device__ float2 g_Kff[SEQ * KVH * DH];           // 4 MB  roped k, float-float
__device__ float g_V[SEQ * KVH * DH];              // 2 MB
__device__ float g_AO[SEQ * QH * DH];              // 8 MB
__device__ float g_S[4 * (size_t)SEQ * SEQ];       // 64 MB: score slabs for 4 heads
__device__ float g_cos[SEQ * 32];
__device__ float g_sin[SEQ * 32];

// ---------------- float-float primitives ----------------
__device__ __forceinline__ void ff_mac(float& h, float& l, float a, float b) {
    float p = a * b;
    float e = fmaf(a, b, -p);       // exact product error
    float s = h + p;
    float bb = s - h;
    float err = (h - (s - bb)) + (p - bb);
    h = s;
    l += err + e;
}

// ---------------- RoPE table: bit-match the reference's f32 op chain ----------------
__global__ void rope_table_kernel() {
    int idx = blockIdx.x * blockDim.x + threadIdx.x;
    if (idx >= SEQ * 32) return;
    int i = idx & 31;
    int pos = idx >> 5;
    float p32 = (float)pow(10000.0, (double)i / 32.0);  // CR f32 of 10000^e
    float invf = 1.0f / p32;                            // f32 division like ref
    float ang = (float)pos * invf;                      // f32 product like ref
    const double TWO_PI = 6.283185307179586476925286766559;
    double dr = (double)ang;
    dr -= TWO_PI * floor(dr / TWO_PI + 0.5);            // exact reduction of f32 angle
    g_cos[idx] = (float)cos(dr);
    g_sin[idx] = (float)sin(dr);
}

// ---------------- tiled NT GEMM -> float-float output (Q,K projections) ----------------
__global__ __launch_bounds__(256) void gemm_nt_ff(const float* __restrict__ A,
                                                  const float* __restrict__ B,
                                                  float2* __restrict__ C,
                                                  int M, int N, int K) {
    __shared__ float As[16][68];
    __shared__ float Bs[16][68];
    int bm = blockIdx.y * 64, bn = blockIdx.x * 64;
    int tid = threadIdx.x;
    int tx = tid & 15, ty = tid >> 4;
    float ah[4][4] = {}, al[4][4] = {};
    for (int k0 = 0; k0 < K; k0 += 16) {
#pragma unroll
        for (int t = 0; t < 4; t++) {
            int idx = tid + t * 256;
            int r = idx >> 4, kk = idx & 15;
            As[kk][r] = A[(size_t)(bm + r) * K + k0 + kk];
            Bs[kk][r] = B[(size_t)(bn + r) * K + k0 + kk];
        }
        __syncthreads();
#pragma unroll
        for (int kk = 0; kk < 16; kk++) {
            float a[4], b[4];
#pragma unroll
            for (int i = 0; i < 4; i++) a[i] = As[kk][ty * 4 + i];
#pragma unroll
            for (int j = 0; j < 4; j++) b[j] = Bs[kk][tx * 4 + j];
#pragma unroll
            for (int i = 0; i < 4; i++)
#pragma unroll
                for (int j = 0; j < 4; j++) ff_mac(ah[i][j], al[i][j], a[i], b[j]);
        }
        __syncthreads();
    }
#pragma unroll
    for (int i = 0; i < 4; i++)
#pragma unroll
        for (int j = 0; j < 4; j++) {
            float hh = ah[i][j] + al[i][j];               // renormalize
            float ll = al[i][j] - (hh - ah[i][j]);
            C[(size_t)(bm + ty * 4 + i) * N + bn + tx * 4 + j] = make_float2(hh, ll);
        }
}

// ---------------- tiled NT GEMM fp32 (V proj, out proj) ----------------
__global__ __launch_bounds__(256) void gemm_nt(const float* __restrict__ A,
                                               const float* __restrict__ B,
                                               float* __restrict__ C,
                                               int M, int N, int K) {
    __shared__ float As[16][68];
    __shared__ float Bs[16][68];
    int bm = blockIdx.y * 64, bn = blockIdx.x * 64;
    int tid = threadIdx.x;
    int tx = tid & 15, ty = tid >> 4;
    float acc[4][4] = {};
    for (int k0 = 0; k0 < K; k0 += 16) {
#pragma unroll
        for (int t = 0; t < 4; t++) {
            int idx = tid + t * 256;
            int r = idx >> 4, kk = idx & 15;
            As[kk][r] = A[(size_t)(bm + r) * K + k0 + kk];
            Bs[kk][r] = B[(size_t)(bn + r) * K + k0 + kk];
        }
        __syncthreads();
#pragma unroll
        for (int kk = 0; kk < 16; kk++) {
            float a[4], b[4];
#pragma unroll
            for (int i = 0; i < 4; i++) a[i] = As[kk][ty * 4 + i];
#pragma unroll
            for (int j = 0; j < 4; j++) b[j] = Bs[kk][tx * 4 + j];
#pragma unroll
            for (int i = 0; i < 4; i++)
#pragma unroll
                for (int j = 0; j < 4; j++) acc[i][j] += a[i] * b[j];
        }
        __syncthreads();
    }
#pragma unroll
    for (int i = 0; i < 4; i++)
#pragma unroll
        for (int j = 0; j < 4; j++)
            C[(size_t)(bm + ty * 4 + i) * N + bn + tx * 4 + j] = acc[i][j];
}

// ---------------- RoPE apply on float-float arrays ----------------
__global__ void rope_ff(float2* __restrict__ X, int n_heads) {
    int idx = blockIdx.x * blockDim.x + threadIdx.x;
    int total = SEQ * n_heads * 32;
    if (idx >= total) return;
    int i = idx % 32;
    int h = (idx / 32) % n_heads;
    int pos = idx / (32 * n_heads);
    double c = (double)g_cos[pos * 32 + i];
    double s = (double)g_sin[pos * 32 + i];
    float2* row = X + (size_t)pos * (n_heads * DH) + h * DH;
    double x1 = (double)row[i].x + (double)row[i].y;
    double x2 = (double)row[i + 32].x + (double)row[i + 32].y;
    double r1 = x1 * c - x2 * s;
    double r2 = x2 * c + x1 * s;
    float h1 = (float)r1, h2 = (float)r2;
    row[i]      = make_float2(h1, (float)(r1 - (double)h1));
    row[i + 32] = make_float2(h2, (float)(r2 - (double)h2));
}

// monotone float->uint map (order-preserving)
__device__ __forceinline__ unsigned fmap(float f) {
    unsigned u = __float_as_uint(f);
    return (u & 0x80000000u) ? ~u : (u | 0x80000000u);
}

// ---------------- score GEMM (ff): 64x64 tiles, 4 heads batched via blockIdx.y ----------------
// dynamic smem: Qh/Ql/Kh/Kl each [64][65] floats = 66560 B total
__global__ __launch_bounds__(256) void score_ff4(int hbase) {
    extern __shared__ float sm[];
    float (*Qh)[65] = (float(*)[65])sm;
    float (*Ql)[65] = (float(*)[65])(sm + 4160);
    float (*Kh)[65] = (float(*)[65])(sm + 8320);
    float (*Kl)[65] = (float(*)[65])(sm + 12480);
    int tid = threadIdx.x;
    int hh = blockIdx.y;
    int h = hbase + hh;
    int t = blockIdx.x;
    int bi = (int)((sqrtf(8.0f * (float)t + 1.0f) - 1.0f) * 0.5f);
    while ((bi + 1) * (bi + 2) / 2 <= t) bi++;
    while (bi * (bi + 1) / 2 > t) bi--;
    int bj = t - bi * (bi + 1) / 2;
    int qi0 = bi * 64, j0 = bj * 64;
    int kvh = h >> 2;
    float* Sh = g_S + (size_t)hh * SEQ * SEQ;

    // load tiles transposed: [dim][row]
#pragma unroll
    for (int p = 0; p < 16; p++) {
        int idx = tid + p * 256;
        int d = idx & 63, r = idx >> 6;
        float2 v = g_Qff[(size_t)(qi0 + r) * (QH * DH) + h * DH + d];
        Qh[d][r] = v.x; Ql[d][r] = v.y;
        float2 w = g_Kff[(size_t)(j0 + r) * (KVH * DH) + kvh * DH + d];
        Kh[d][r] = w.x; Kl[d][r] = w.y;
    }
    __syncthreads();

    int tx = tid & 15, ty = tid >> 4;   // cols tx+16j, rows ty+16i (conflict-free)
    float ah[4][4] = {}, al[4][4] = {};
#pragma unroll 4
    for (int kk = 0; kk < 64; kk++) {
        float qh_[4], ql_[4], kh_[4], kl_[4];
#pragma unroll
        for (int i = 0; i < 4; i++) { qh_[i] = Qh[kk][ty + 16 * i]; ql_[i] = Ql[kk][ty + 16 * i]; }
#pragma unroll
        for (int j = 0; j < 4; j++) { kh_[j] = Kh[kk][tx + 16 * j]; kl_[j] = Kl[kk][tx + 16 * j]; }
#pragma unroll
        for (int i = 0; i < 4; i++)
#pragma unroll
            for (int j = 0; j < 4; j++) {
                ff_mac(ah[i][j], al[i][j], qh_[i], kh_[j]);
                al[i][j] += qh_[i] * kl_[j] + ql_[i] * kh_[j];
            }
    }
#pragma unroll
    for (int i = 0; i < 4; i++) {
        int qi = qi0 + ty + 16 * i;
#pragma unroll
        for (int j = 0; j < 4; j++) {
            int jj = j0 + tx + 16 * j;
            if (jj <= qi)
                Sh[(size_t)qi * SEQ + jj] = (ah[i][j] + al[i][j]) * 0.125f;
        }
    }
}

// ---------------- attention phase B: block per (query row, head-in-group) ----------------
__global__ __launch_bounds__(256) void attn_row4(int hbase) {
    __shared__ float sc[SEQ];
    __shared__ int hist[2048];
    __shared__ int psum[256];
    __shared__ unsigned long long buf[256];
    __shared__ unsigned bufrm[8];
    __shared__ unsigned long long wred[8];
    __shared__ unsigned long long s_mx;
    __shared__ float fred[8];
    __shared__ float s_smax, s_den;
    __shared__ unsigned s_thr;
    __shared__ int s_b, s_k, s_cnt;
    __shared__ float4 red4[16][16];

    int tid = threadIdx.x, lane = tid & 31, wid = tid >> 5;
    int qi = blockIdx.x;
    int hh = blockIdx.y;
    int h = hbase + hh;
    int kvh = h >> 2;
    int len = qi + 1;

    const float* Srow = g_S + (size_t)hh * SEQ * SEQ + (size_t)qi * SEQ;
    for (int j = tid; j < len; j += 256) sc[j] = Srow[j];
    __syncthreads();

    // ---- row max ----
    {
        float lm = -INFINITY;
        for (int j = tid; j < len; j += 256) lm = fmaxf(lm, sc[j]);
#pragma unroll
        for (int o = 16; o; o >>= 1) lm = fmaxf(lm, __shfl_xor_sync(0xffffffffu, lm, o));
        if (lane == 0) fred[wid] = lm;
        __syncthreads();
        if (tid == 0) {
            float mm = fred[0];
            for (int w = 1; w < 8; w++) mm = fmaxf(mm, fred[w]);
            s_smax = mm;
        }
        __syncthreads();
    }
    float smax = s_smax;

    // ---- exact 64th-largest threshold ----
    unsigned thr = 0;
    if (len > TOPK) {
        for (int i = tid; i < 2048; i += 256) hist[i] = 0;
        __syncthreads();
        for (int j = tid; j < len; j += 256)
            atomicAdd(&hist[fmap(sc[j]) >> 21], 1);
        __syncthreads();
        {
            int cs = 0;
#pragma unroll
            for (int b = 0; b < 8; b++) cs += hist[tid * 8 + b];
            psum[tid] = cs;
        }
        __syncthreads();
        if (tid == 0) {
            int kneed = TOPK, cum = 0, chunk = 0;
            for (int t = 255; t >= 0; t--) {
                if (cum + psum[t] >= kneed) { chunk = t; break; }
                cum += psum[t];
            }
            int b = chunk * 8;
            for (int bb = chunk * 8 + 7; bb >= chunk * 8; bb--) {
                if (cum + hist[bb] >= kneed) { b = bb; break; }
                cum += hist[bb];
            }
            s_b = b;
            s_k = kneed - cum;
        }
        __syncthreads();
        int b1 = s_b, k1 = s_k;

        for (int i = tid; i < 2048; i += 256) hist[i] = 0;
        __syncthreads();
        for (int j = tid; j < len; j += 256) {
            unsigned u = fmap(sc[j]);
            if ((int)(u >> 21) == b1) atomicAdd(&hist[(u >> 10) & 0x7FF], 1);
        }
        __syncthreads();
        {
            int cs = 0;
#pragma unroll
            for (int b = 0; b < 8; b++) cs += hist[tid * 8 + b];
            psum[tid] = cs;
        }
        __syncthreads();
        if (tid == 0) {
            int kneed = k1, cum = 0, chunk = 0;
            for (int t = 255; t >= 0; t--) {
                if (cum + psum[t] >= kneed) { chunk = t; break; }
                cum += psum[t];
            }
            int b = chunk * 8;
            for (int bb = chunk * 8 + 7; bb >= chunk * 8; bb--) {
                if (cum + hist[bb] >= kneed) { b = bb; break; }
                cum += hist[bb];
            }
            s_b = b;
            s_k = kneed - cum;
            s_cnt = 0;
        }
        __syncthreads();
        int b2 = s_b, k2 = s_k;
        unsigned pref = ((unsigned)b1 << 11) | (unsigned)b2;

        if (tid < 8) bufrm[tid] = 0;
        __syncthreads();
        for (int j = tid; j < len; j += 256) {
            unsigned u = fmap(sc[j]);
            if ((u >> 10) == pref) {
                int p = atomicAdd(&s_cnt, 1);
                if (p < 256) buf[p] = ((unsigned long long)u << 11) | (unsigned)j;
            }
        }
        __syncthreads();
        int cnt = s_cnt;

        if (cnt <= 256) {
            for (int p = 0; p < k2; p++) {
                unsigned long long my = 0ull;
                if (tid < cnt && !((bufrm[tid >> 5] >> (tid & 31)) & 1u)) my = buf[tid];
                unsigned long long v = my;
#pragma unroll
                for (int o = 16; o; o >>= 1) {
                    unsigned long long t = __shfl_xor_sync(0xffffffffu, v, o);
                    if (t > v) v = t;
                }
                if (lane == 0) wred[wid] = v;
                __syncthreads();
                if (tid == 0) {
                    unsigned long long mx = wred[0];
                    for (int w = 1; w < 8; w++)
                        if (wred[w] > mx) mx = wred[w];
                    s_mx = mx;
                    if (p == k2 - 1) s_thr = (unsigned)(mx >> 11);
                }
                __syncthreads();
                if (my == s_mx && my != 0ull) bufrm[tid >> 5] |= 1u << (tid & 31);
                __syncthreads();
            }
        } else {
            for (int i = tid; i < 64; i += 256) hist[i] = 0;
            __syncthreads();
            unsigned* rm = (unsigned*)hist;
            for (int p = 0; p < TOPK; p++) {
                unsigned long long local = 0ull;
                for (int j = tid; j < len; j += 256) {
                    if (!((rm[j >> 5] >> (j & 31)) & 1u)) {
                        unsigned long long key =
                            ((unsigned long long)fmap(sc[j]) << 11) | (unsigned)j;
                        if (key > local) local = key;
                    }
                }
#pragma unroll
                for (int o = 16; o; o >>= 1) {
                    unsigned long long t = __shfl_xor_sync(0xffffffffu, local, o);
                    if (t > local) local = t;
                }
                if (lane == 0) wred[wid] = local;
                __syncthreads();
                if (tid == 0) {
                    unsigned long long mx = wred[0];
                    for (int w = 1; w < 8; w++)
                        if (wred[w] > mx) mx = wred[w];
                    int j = (int)(mx & 0x7FFull);
                    rm[j >> 5] |= 1u << (j & 31);
                    if (p == TOPK - 1) s_thr = (unsigned)(mx >> 11);
                }
                __syncthreads();
            }
        }
        thr = s_thr;
    }

    // ---- weights + denominator (deterministic reduction order) ----
    float part = 0.f;
    __syncthreads();
    for (int j = tid; j < len; j += 256) {
        float v = sc[j];
        float wv = (fmap(v) >= thr) ? expf(v - smax) : 0.f;
        sc[j] = wv;
        part += wv;
    }
#pragma unroll
    for (int o = 16; o; o >>= 1) part += __shfl_xor_sync(0xffffffffu, part, o);
    if (lane == 0) fred[wid] = part;
    __syncthreads();
    if (tid == 0) {
        float d = 0.f;
        for (int w = 0; w < 8; w++) d += fred[w];
        s_den = d;
    }
    __syncthreads();
    float inv = 1.f / s_den;

    // ---- AV: 16 j-groups x 16 float4-dims, deterministic tree ----
    {
        int g = tid >> 4, d4 = tid & 15;
        float4 a = make_float4(0.f, 0.f, 0.f, 0.f);
        for (int j = g; j < len; j += 16) {
            float wv = sc[j];
            if (wv != 0.f) {
                float4 vv = *((const float4*)(g_V + (size_t)j * (KVH * DH) + kvh * DH) + d4);
                a.x += wv * vv.x; a.y += wv * vv.y;
                a.z += wv * vv.z; a.w += wv * vv.w;
            }
        }
        red4[g][d4] = a;
    }
    __syncthreads();
    if (tid < 16) {
        float4 a = make_float4(0.f, 0.f, 0.f, 0.f);
        for (int g = 0; g < 16; g++) {
            float4 v = red4[g][tid];
            a.x += v.x; a.y += v.y; a.z += v.z; a.w += v.w;
        }
        a.x *= inv; a.y *= inv; a.z *= inv; a.w *= inv;
        *((float4*)(g_AO + (size_t)qi * (QH * DH) + h * DH) + tid) = a;
    }
}

// ---------------- launch ----------------
extern "C" void kernel_launch(void* const* d_in, const int* in_sizes, int n_in,
                              void* d_out, int out_size) {
    (void)out_size;
    int ixv = -1, big[2] = {-1, -1}, sml[2] = {-1, -1};
    int nb = 0, ns = 0;
    for (int i = 0; i < n_in; i++) {
        if (in_sizes[i] == SEQ * DMODEL && ixv < 0) ixv = i;
        else if (in_sizes[i] == QH * DH * DMODEL && nb < 2) big[nb++] = i;
        else if (in_sizes[i] == KVH * DH * DMODEL && ns < 2) sml[ns++] = i;
    }
    if (ixv < 0 || nb < 2 || ns < 2) {
        ixv = 0; big[0] = 1; big[1] = 4; sml[0] = 2; sml[1] = 3;
    }
    const float* x  = (const float*)d_in[ixv];
    const float* Wq = (const float*)d_in[big[0]];
    const float* Wo = (const float*)d_in[big[1]];
    const float* Wk = (const float*)d_in[sml[0]];
    const float* Wv = (const float*)d_in[sml[1]];
    float* out = (float*)d_out;

    float2 *Qff, *Kff;
    float *V, *AO;
    cudaGetSymbolAddress((void**)&Qff, g_Qff);
    cudaGetSymbolAddress((void**)&Kff, g_Kff);
    cudaGetSymbolAddress((void**)&V, g_V);
    cudaGetSymbolAddress((void**)&AO, g_AO);

    static int smem_set = 0;
    if (!smem_set) {
        cudaFuncSetAttribute(score_ff4, cudaFuncAttributeMaxDynamicSharedMemorySize, 66560);
        smem_set = 1;
    }

    rope_table_kernel<<<(SEQ * 32 + 255) / 256, 256>>>();

    gemm_nt_ff<<<dim3((QH * DH) / 64, SEQ / 64), 256>>>(x, Wq, Qff, SEQ, QH * DH, DMODEL);
    gemm_nt_ff<<<dim3((KVH * DH) / 64, SEQ / 64), 256>>>(x, Wk, Kff, SEQ, KVH * DH, DMODEL);
    gemm_nt<<<dim3((KVH * DH) / 64, SEQ / 64), 256>>>(x, Wv, V, SEQ, KVH * DH, DMODEL);

    rope_ff<<<(SEQ * QH * 32) / 256, 256>>>(Qff, QH);
    rope_ff<<<(SEQ * KVH * 32) / 256, 256>>>(Kff, KVH);

    const int NT = (SEQ / 64) * (SEQ / 64 + 1) / 2;  // 528 triangular tiles
    for (int g = 0; g < 4; g++) {
        score_ff4<<<dim3(NT, 4), 256, 66560>>>(g * 4);
        attn_row4<<<dim3(SEQ, 4), 256>>>(g * 4);
    }

    gemm_nt<<<dim3(DMODEL / 64, SEQ / 64), 256>>>(AO, Wo, out, SEQ, DMODEL, QH * DH);
}